// round 1
// baseline (speedup 1.0000x reference)
#include <cuda_runtime.h>
#include <cuda_bf16.h>
#include <math.h>
#include <stdint.h>

// ---------------- problem constants ----------------
#define B 128
#define S_SRC 128
#define S_TRG 64
#define H 1024
#define LEXD 300
#define NTD 128
#define CTXD 300
#define ATT 100
#define ANS 556           // LEXD + 2*NTD
#define G4 4096           // 4*H
#define KENC 1344         // 1024 + 300 padded to 32
#define KDEC 1888         // 1024 + 556 + 300 padded to 32

// ---------------- scratch (device globals; no allocation allowed) ----------------
__device__ float g_Wenc[(size_t)G4 * KENC];     // [Whh | Wih | pad]
__device__ float g_Wdec[(size_t)G4 * KDEC];     // [Whh | Wih(856) | pad]
__device__ float g_srcemb[(size_t)B * S_SRC * LEXD];
__device__ float g_ansemb[(size_t)B * S_TRG * ANS];
__device__ float g_eh[B * H];
__device__ float g_ec[B * H];
__device__ float g_dh[B * H];
__device__ float g_dc[B * H];
__device__ float g_ctx[B * CTXD];
__device__ float g_srchid[(size_t)B * S_SRC * H];
__device__ float g_qkey[(size_t)B * S_SRC * ATT];
__device__ float g_qval[(size_t)B * S_SRC * CTXD];
__device__ float g_tmp[B * 2048];

// ---------------- setup: build concatenated weights, zero states ----------------
__global__ void setup_kernel(const float* __restrict__ encWhh, const float* __restrict__ encWih,
                             const float* __restrict__ decWhh, const float* __restrict__ decWih) {
    const int64_t n1 = (int64_t)G4 * KENC;
    const int64_t n2 = (int64_t)G4 * KDEC;
    int64_t stride = (int64_t)gridDim.x * blockDim.x;
    for (int64_t i = (int64_t)blockIdx.x * blockDim.x + threadIdx.x; i < n2; i += stride) {
        if (i < n1) {
            int j = (int)(i / KENC), k = (int)(i % KENC);
            float v = (k < 1024) ? encWhh[(int64_t)j * 1024 + k]
                    : (k < 1324) ? encWih[(int64_t)j * 300 + (k - 1024)] : 0.f;
            g_Wenc[i] = v;
        }
        {
            int j = (int)(i / KDEC), k = (int)(i % KDEC);
            float v = (k < 1024) ? decWhh[(int64_t)j * 1024 + k]
                    : (k < 1880) ? decWih[(int64_t)j * 856 + (k - 1024)] : 0.f;
            g_Wdec[i] = v;
        }
        if (i < B * H) { g_eh[i] = 0.f; g_ec[i] = 0.f; }
    }
}

// ---------------- embedding gathers ----------------
__global__ void gather_kernel(const int* __restrict__ src_seqs, const int* __restrict__ trg_nt,
                              const int* __restrict__ par_nt, const int* __restrict__ par_lex,
                              const float* __restrict__ lex_emb, const float* __restrict__ nt_emb) {
    const int64_t nse = (int64_t)B * S_SRC * LEXD;   // 4,915,200
    const int64_t nae = (int64_t)B * S_TRG * ANS;    // 4,554,752
    int64_t stride = (int64_t)gridDim.x * blockDim.x;
    for (int64_t i = (int64_t)blockIdx.x * blockDim.x + threadIdx.x; i < nse; i += stride) {
        int d = (int)(i % LEXD);
        int bs = (int)(i / LEXD);
        g_srcemb[i] = lex_emb[(int64_t)src_seqs[bs] * LEXD + d];
        if (i < nae) {
            int d2 = (int)(i % ANS);
            int bt = (int)(i / ANS);
            float v;
            if (d2 < 128)       v = nt_emb[(int64_t)trg_nt[bt] * NTD + d2];
            else if (d2 < 256)  v = nt_emb[(int64_t)par_nt[bt] * NTD + (d2 - 128)];
            else                v = lex_emb[(int64_t)par_lex[bt] * LEXD + (d2 - 256)];
            g_ansemb[i] = v;
        }
    }
}

// ---------------- fused LSTM step: GEMM (all 4 gates) + gate math ----------------
// grid: 128 blocks (each owns 8 hidden cols x 4 gates), 256 threads.
// MODE 0 = encoder (A = [h | src_emb_s]), MODE 1 = decoder (A = [h | ans_t | ctx])
template<int MODE>
__global__ __launch_bounds__(256) void step_kernel(const float* __restrict__ bias,
                                                   const int* __restrict__ lens,
                                                   float* __restrict__ out, int s) {
    __shared__ float shA[128][33];
    __shared__ float shW[32][33];
    const float* __restrict__ W = (MODE == 0) ? g_Wenc : g_Wdec;
    const int KT  = (MODE == 0) ? (KENC / 32) : (KDEC / 32);
    const int LDW = (MODE == 0) ? KENC : KDEC;
    const float* __restrict__ hin = (MODE == 0) ? g_eh : g_dh;

    int t = threadIdx.x;
    int j0 = blockIdx.x * 8;
    int jj = t & 7, bg = t >> 3;     // jj: 0..7 column, bg: 0..31 (4 batch rows each)
    float acc[4][4];
#pragma unroll
    for (int g = 0; g < 4; g++)
#pragma unroll
        for (int i = 0; i < 4; i++) acc[g][i] = 0.f;

    for (int kt = 0; kt < KT; kt++) {
        int k0 = kt * 32;
        // load A tile 128x32
#pragma unroll
        for (int m = 0; m < 16; m++) {
            int idx = m * 256 + t;
            int row = idx >> 5, kk = idx & 31;
            int k = k0 + kk;
            float v;
            if (MODE == 0) {
                v = (k < 1024) ? hin[row * H + k]
                  : (k < 1324) ? g_srcemb[((int64_t)row * S_SRC + s) * LEXD + (k - 1024)] : 0.f;
            } else {
                v = (k < 1024) ? hin[row * H + k]
                  : (k < 1580) ? g_ansemb[((int64_t)row * S_TRG + s) * ANS + (k - 1024)]
                  : (k < 1880) ? g_ctx[row * CTXD + (k - 1580)] : 0.f;
            }
            shA[row][kk] = v;
        }
        // load W tile 32x32 (4 gates x 8 cols)
#pragma unroll
        for (int m = 0; m < 4; m++) {
            int idx = m * 256 + t;
            int wrow = idx >> 5, kk = idx & 31;
            int gate = wrow >> 3, jl = wrow & 7;
            shW[wrow][kk] = W[(int64_t)(gate * 1024 + j0 + jl) * LDW + k0 + kk];
        }
        __syncthreads();
#pragma unroll
        for (int kk = 0; kk < 32; kk++) {
            float wv0 = shW[jj][kk];
            float wv1 = shW[8 + jj][kk];
            float wv2 = shW[16 + jj][kk];
            float wv3 = shW[24 + jj][kk];
#pragma unroll
            for (int i = 0; i < 4; i++) {
                float hv = shA[bg * 4 + i][kk];
                acc[0][i] = fmaf(wv0, hv, acc[0][i]);
                acc[1][i] = fmaf(wv1, hv, acc[1][i]);
                acc[2][i] = fmaf(wv2, hv, acc[2][i]);
                acc[3][i] = fmaf(wv3, hv, acc[3][i]);
            }
        }
        __syncthreads();
    }

    int col = j0 + jj;
    float b0 = bias[col], b1 = bias[1024 + col], b2 = bias[2048 + col], b3 = bias[3072 + col];
    float* hbuf = (MODE == 0) ? g_eh : g_dh;
    float* cbuf = (MODE == 0) ? g_ec : g_dc;
#pragma unroll
    for (int i = 0; i < 4; i++) {
        int b = bg * 4 + i;
        float zi = acc[0][i] + b0;
        float zf = acc[1][i] + b1;
        float zg = acc[2][i] + b2;
        float zo = acc[3][i] + b3;
        float cold = cbuf[b * H + col];
        float si = 1.f / (1.f + expf(-zi));
        float sf = 1.f / (1.f + expf(-zf));
        float so = 1.f / (1.f + expf(-zo));
        float c2 = sf * cold + si * tanhf(zg);
        float h2 = so * tanhf(c2);
        if (MODE == 0) {
            bool valid = s < lens[b];
            if (valid) { hbuf[b * H + col] = h2; cbuf[b * H + col] = c2; }
            g_srchid[((int64_t)b * S_SRC + s) * H + col] = valid ? h2 : 0.f;
        } else {
            hbuf[b * H + col] = h2;
            cbuf[b * H + col] = c2;
            out[((int64_t)b * S_TRG + s) * H + col] = h2;
        }
    }
}

// ---------------- generic fp32 GEMM: C = act(A[M,K] @ W[N,K]^T + bias) ----------------
// ACT: 0 none, 1 relu, 2 tanh. A/C chosen from device globals via selectors.
template<int ACT>
__global__ __launch_bounds__(256) void gemm_kernel(int asel, const float* __restrict__ Wm,
                                                   const float* __restrict__ bias, int csel,
                                                   int M, int N, int K) {
    const float* __restrict__ A =
        (asel == 0) ? g_srchid : (asel == 1) ? g_eh : (asel == 2) ? g_ec : g_tmp;
    float* __restrict__ C =
        (csel == 0) ? g_qkey : (csel == 1) ? g_qval : (csel == 2) ? g_tmp
      : (csel == 3) ? g_dh : g_dc;

    __shared__ float sA[64][17];
    __shared__ float sW[64][17];
    int t = threadIdx.x;
    int m0 = blockIdx.y * 64, n0 = blockIdx.x * 64;
    int tx = t & 15, ty = t >> 4;
    float acc[4][4];
#pragma unroll
    for (int i = 0; i < 4; i++)
#pragma unroll
        for (int j = 0; j < 4; j++) acc[i][j] = 0.f;

    for (int k0 = 0; k0 < K; k0 += 16) {
#pragma unroll
        for (int q = 0; q < 4; q++) {
            int idx = q * 256 + t;
            int r = idx >> 4, kk = idx & 15;
            int gm = m0 + r;
            sA[r][kk] = (gm < M) ? A[(int64_t)gm * K + k0 + kk] : 0.f;
            int gn = n0 + r;
            sW[r][kk] = (gn < N) ? Wm[(int64_t)gn * K + k0 + kk] : 0.f;
        }
        __syncthreads();
#pragma unroll
        for (int kk = 0; kk < 16; kk++) {
            float av[4], wv[4];
#pragma unroll
            for (int i = 0; i < 4; i++) av[i] = sA[ty * 4 + i][kk];
#pragma unroll
            for (int j = 0; j < 4; j++) wv[j] = sW[tx * 4 + j][kk];
#pragma unroll
            for (int i = 0; i < 4; i++)
#pragma unroll
                for (int j = 0; j < 4; j++) acc[i][j] = fmaf(av[i], wv[j], acc[i][j]);
        }
        __syncthreads();
    }
#pragma unroll
    for (int i = 0; i < 4; i++) {
        int gm = m0 + ty * 4 + i;
        if (gm >= M) continue;
#pragma unroll
        for (int j = 0; j < 4; j++) {
            int gn = n0 + tx * 4 + j;
            if (gn >= N) continue;
            float v = acc[i][j] + bias[gn];
            if (ACT == 1) v = fmaxf(v, 0.f);
            if (ACT == 2) v = tanhf(v);
            C[(int64_t)gm * N + gn] = v;
        }
    }
}

// ---------------- per-decoder-step attention ----------------
// 128 blocks (one per batch element), 128 threads.
__global__ __launch_bounds__(128) void attn_kernel(const float* __restrict__ Wa,
                                                   const float* __restrict__ ba,
                                                   const int* __restrict__ lens) {
    __shared__ float hs[1024];
    __shared__ float ak[112];
    __shared__ float en[128];
    __shared__ float red[32];
    int b = blockIdx.x;
    int tid = threadIdx.x;
    int lane = tid & 31, wid = tid >> 5;

#pragma unroll
    for (int m = 0; m < 8; m++) hs[m * 128 + tid] = g_dh[b * H + m * 128 + tid];
    __syncthreads();

    // a_key = tanh(h @ Wa^T + ba)   (100 rows, 4 warps)
    for (int k = wid; k < ATT; k += 4) {
        float p = 0.f;
        const float* wr = Wa + (int64_t)k * H;
#pragma unroll
        for (int m = 0; m < 32; m++) p = fmaf(wr[m * 32 + lane], hs[m * 32 + lane], p);
        for (int o = 16; o; o >>= 1) p += __shfl_xor_sync(0xffffffffu, p, o);
        if (lane == 0) ak[k] = tanhf(p + ba[k]);
    }
    __syncthreads();

    // energy + softmax over S_SRC (one value per thread)
    int L = lens[b];
    float e;
    {
        const float* qk = g_qkey + ((int64_t)b * S_SRC + tid) * ATT;
        float p = 0.f;
#pragma unroll 4
        for (int d = 0; d < ATT; d++) p = fmaf(qk[d], ak[d], p);
        e = (tid < L) ? p : -1e9f;
    }
    float mx = e;
    for (int o = 16; o; o >>= 1) mx = fmaxf(mx, __shfl_xor_sync(0xffffffffu, mx, o));
    if (lane == 0) red[wid] = mx;
    __syncthreads();
    mx = fmaxf(fmaxf(red[0], red[1]), fmaxf(red[2], red[3]));
    float ex = expf(e - mx);
    float sm = ex;
    for (int o = 16; o; o >>= 1) sm += __shfl_xor_sync(0xffffffffu, sm, o);
    if (lane == 0) red[8 + wid] = sm;
    __syncthreads();
    sm = red[8] + red[9] + red[10] + red[11];
    en[tid] = ex / sm;
    __syncthreads();

    // context = sum_s w[s] * q_value[b,s,:]
    for (int d = tid; d < CTXD; d += 128) {
        float c = 0.f;
        for (int s2 = 0; s2 < S_SRC; s2++)
            c = fmaf(en[s2], g_qval[((int64_t)b * S_SRC + s2) * CTXD + d], c);
        g_ctx[b * CTXD + d] = c;
    }
}

// ---------------- launcher ----------------
extern "C" void kernel_launch(void* const* d_in, const int* in_sizes, int n_in,
                              void* d_out, int out_size) {
    const int*   src_seqs = (const int*)d_in[0];
    const int*   src_len  = (const int*)d_in[1];
    const int*   trg_nt   = (const int*)d_in[2];
    const int*   par_nt   = (const int*)d_in[3];
    const int*   par_lex  = (const int*)d_in[4];
    const float* lex_emb  = (const float*)d_in[5];
    const float* nt_emb   = (const float*)d_in[6];
    const float* enc_Wih  = (const float*)d_in[7];
    const float* enc_Whh  = (const float*)d_in[8];
    const float* enc_b    = (const float*)d_in[9];
    const float* dec_Wih  = (const float*)d_in[10];
    const float* dec_Whh  = (const float*)d_in[11];
    const float* dec_b    = (const float*)d_in[12];
    const float* Wh1 = (const float*)d_in[13];
    const float* bh1 = (const float*)d_in[14];
    const float* Wh2 = (const float*)d_in[15];
    const float* bh2 = (const float*)d_in[16];
    const float* Wc1 = (const float*)d_in[17];
    const float* bc1 = (const float*)d_in[18];
    const float* Wc2 = (const float*)d_in[19];
    const float* bc2 = (const float*)d_in[20];
    const float* Wa  = (const float*)d_in[21];
    const float* ba  = (const float*)d_in[22];
    const float* Wqk = (const float*)d_in[23];
    const float* bqk = (const float*)d_in[24];
    const float* Wqv = (const float*)d_in[25];
    const float* bqv = (const float*)d_in[26];
    float* out = (float*)d_out;

    setup_kernel<<<2048, 256>>>(enc_Whh, enc_Wih, dec_Whh, dec_Wih);
    gather_kernel<<<2048, 256>>>(src_seqs, trg_nt, par_nt, par_lex, lex_emb, nt_emb);

    // encoder recurrence
    for (int s = 0; s < S_SRC; s++)
        step_kernel<0><<<128, 256>>>(enc_b, src_len, out, s);

    // attention keys / values (step-invariant)
    {
        dim3 gk((ATT + 63) / 64, (B * S_SRC) / 64);
        gemm_kernel<2><<<gk, 256>>>(0, Wqk, bqk, 0, B * S_SRC, ATT, H);
        dim3 gv((CTXD + 63) / 64, (B * S_SRC) / 64);
        gemm_kernel<0><<<gv, 256>>>(0, Wqv, bqv, 1, B * S_SRC, CTXD, H);
    }

    // decoder init MLPs: dh = relu(hT@Wh1^T+bh1)@Wh2^T+bh2 ; dc likewise
    {
        dim3 g1(2048 / 64, 2);
        dim3 g2(1024 / 64, 2);
        gemm_kernel<1><<<g1, 256>>>(1, Wh1, bh1, 2, B, 2048, H);
        gemm_kernel<0><<<g2, 256>>>(3, Wh2, bh2, 3, B, H, 2048);
        gemm_kernel<1><<<g1, 256>>>(2, Wc1, bc1, 2, B, 2048, H);
        gemm_kernel<0><<<g2, 256>>>(3, Wc2, bc2, 4, B, H, 2048);
    }

    // decoder recurrence with attention
    for (int t = 0; t < S_TRG; t++) {
        attn_kernel<<<128, 128>>>(Wa, ba, src_len);
        step_kernel<1><<<128, 256>>>(dec_b, src_len, out, t);
    }
}